// round 7
// baseline (speedup 1.0000x reference)
#include <cuda_runtime.h>
#include <cstdint>

// SNN: fc1(21->100) -> 25-step Leaky -> fc2(100->10) -> Leaky
// Dense fused pass, bitwise-identical numerics to the passing R4/R5 kernels:
//  - cur1: acc=0, FMA k ascending, + b1 at end
//  - cur2: ascending-j chain; fma2(s,w,acc) with s in {0,1} is EXACTLY
//    add(acc,w) when s=1 and identity when s=0 -> bitwise == sparse ordered
//    column sum. + b2 pair-adds at end (per-lane scalar RN).
//  - layer-1: mem = fma(beta,mem,cur); if(prev spike) mem = fsub(mem,1.0)
//  - layer-2: mem = fsub(fma(beta,mem,cur), prev_spk)
// No data-dependent branches in the hot loop: zero divergence, uniform
// broadcast LDS of W2 rows, full unroll, deep ILP (5 indep fma2 chains).

#define BETA    0.99f
#define NSTEPS  25
#define H1      100
#define H2      10
#define NIN     21
#define TPB     128

typedef unsigned long long u64;
typedef unsigned int u32;

__device__ __forceinline__ u64 fma2(u64 a, u64 b, u64 c) {
    u64 d;
    asm("fma.rn.f32x2 %0, %1, %2, %3;" : "=l"(d) : "l"(a), "l"(b), "l"(c));
    return d;
}
__device__ __forceinline__ u64 add2(u64 a, u64 b) {
    u64 d;
    asm("add.rn.f32x2 %0, %1, %2;" : "=l"(d) : "l"(a), "l"(b));
    return d;
}
__device__ __forceinline__ void unpack2(u64 v, float& a, float& b) {
    asm("mov.b64 {%0, %1}, %2;" : "=f"(a), "=f"(b) : "l"(v));
}
__device__ __forceinline__ u64 pack_dup(float s) {
    u64 r;
    asm("mov.b64 %0, {%1, %1};" : "=l"(r) : "f"(s));
    return r;
}

// dynamic smem layout (floats):
//   cur1_s : [25][TPB] float4  @ 0      (12800 floats, 51200 B)
//   W2s    : [100][12]         @ 12800  (1200 floats)
//   b2s    : [12]              @ 14000
//   W1s    : [100][24]         @ 14016
//   b1s    : [100]             @ 16416
#define OFF_CUR1 0
#define OFF_W2   12800
#define OFF_B2   14000
#define OFF_W1   14016
#define OFF_B1   16416
#define SMEM_FLOATS 16516
#define SMEM_BYTES (SMEM_FLOATS * 4)

__global__ __launch_bounds__(TPB, 3)
void snn_kernel(const float* __restrict__ x,
                const float* __restrict__ W1,
                const float* __restrict__ b1,
                const float* __restrict__ W2,
                const float* __restrict__ b2,
                float* __restrict__ out,
                int B)
{
    extern __shared__ __align__(16) float smem[];
    float* cur1_s = smem + OFF_CUR1;
    float* W2s    = smem + OFF_W2;
    float* b2s    = smem + OFF_B2;
    float* W1s    = smem + OFF_W1;
    float* b1s    = smem + OFF_B1;

    const int tid = threadIdx.x;

    for (int idx = tid; idx < H1 * NIN; idx += TPB)
        W1s[(idx / NIN) * 24 + (idx % NIN)] = W1[idx];
    for (int idx = tid; idx < H2 * H1; idx += TPB)
        W2s[(idx % H1) * 12 + (idx / H1)] = W2[idx];     // W2 is [10][100]
    for (int idx = tid; idx < H1; idx += TPB) {
        W2s[idx * 12 + 10] = 0.0f;                       // pad cols
        W2s[idx * 12 + 11] = 0.0f;
    }
    if (tid < H1) b1s[tid] = b1[tid];
    if (tid < 12) b2s[tid] = (tid < H2) ? b2[tid] : 0.0f;
    __syncthreads();

    const int sample = blockIdx.x * TPB + tid;
    if (sample >= B) return;

    // ---- x row ----
    float xr[NIN];
    const float* xrow = x + (size_t)sample * NIN;
#pragma unroll
    for (int i = 0; i < NIN; i++) xr[i] = __ldg(xrow + i);

    // ---- cur1 (all 100): acc=0, FMA k ascending, + b1; store to smem ----
#pragma unroll 1
    for (int g = 0; g < 25; g++) {
        float4 cv;
        float* cp = &cv.x;
#pragma unroll
        for (int i = 0; i < 4; i++) {
            const int j = g * 4 + i;
            const float* w = &W1s[j * 24];
            float acc = 0.0f;
#pragma unroll
            for (int k = 0; k < NIN; k++)
                acc = __fmaf_rn(xr[k], w[k], acc);
            cp[i] = __fadd_rn(acc, b1s[j]);
        }
        *(float4*)&cur1_s[(g * TPB + tid) * 4] = cv;
    }

    // ---- state ----
    float mem1[H1];
#pragma unroll
    for (int j = 0; j < H1; j++) mem1[j] = 0.0f;
    u32 Mo0 = 0, Mo1 = 0, Mo2 = 0, Mo3 = 0;   // spike bits, seg = j>>5

    float mem2[H2], spk2[H2];
#pragma unroll
    for (int k = 0; k < H2; k++) { mem2[k] = 0.0f; spk2[k] = 0.0f; }

    const u64 B0 = *(const u64*)&b2s[0];
    const u64 B1 = *(const u64*)&b2s[2];
    const u64 B2 = *(const u64*)&b2s[4];
    const u64 B3 = *(const u64*)&b2s[6];
    const u64 B4 = *(const u64*)&b2s[8];

    float* spkout = out + (size_t)sample * H2;
    float* memout = spkout + (size_t)NSTEPS * B * H2;
    const size_t step_stride = (size_t)B * H2;

#pragma unroll 1
    for (int t = 0; t < NSTEPS; t++) {
        u32 Mn0 = 0, Mn1 = 0, Mn2 = 0, Mn3 = 0;
        u64 a0 = 0ull, a1 = 0ull, a2 = 0ull, a3 = 0ull, a4 = 0ull;

#pragma unroll
        for (int g = 0; g < 25; g++) {
            float4 cv = *(const float4*)&cur1_s[(g * TPB + tid) * 4];
            const float* cp = &cv.x;
#pragma unroll
            for (int i = 0; i < 4; i++) {
                const int j = g * 4 + i;
                const u32 om = (j < 32) ? Mo0 : (j < 64) ? Mo1 : (j < 96) ? Mo2 : Mo3;
                float mv = __fmaf_rn(BETA, mem1[j], cp[i]);
                if ((om >> (j & 31)) & 1u) mv = __fsub_rn(mv, 1.0f);
                mem1[j] = mv;
                const bool sp = mv > 1.0f;
                if (sp) {
                    if (j < 32)      Mn0 |= (1u << (j & 31));
                    else if (j < 64) Mn1 |= (1u << (j & 31));
                    else if (j < 96) Mn2 |= (1u << (j & 31));
                    else             Mn3 |= (1u << (j & 31));
                }
                const u64 s2 = pack_dup(sp ? 1.0f : 0.0f);
                const float* w = &W2s[j * 12];
                ulonglong2 qa = *(const ulonglong2*)(w);
                ulonglong2 qb = *(const ulonglong2*)(w + 4);
                u64        qc = *(const u64*)(w + 8);
                a0 = fma2(s2, qa.x, a0);
                a1 = fma2(s2, qa.y, a1);
                a2 = fma2(s2, qb.x, a2);
                a3 = fma2(s2, qb.y, a3);
                a4 = fma2(s2, qc,   a4);
            }
        }
        Mo0 = Mn0; Mo1 = Mn1; Mo2 = Mn2; Mo3 = Mn3;

        a0 = add2(a0, B0);
        a1 = add2(a1, B1);
        a2 = add2(a2, B2);
        a3 = add2(a3, B3);
        a4 = add2(a4, B4);

        float c[H2];
        unpack2(a0, c[0], c[1]);
        unpack2(a1, c[2], c[3]);
        unpack2(a2, c[4], c[5]);
        unpack2(a3, c[6], c[7]);
        unpack2(a4, c[8], c[9]);

        // ---- layer-2: mem = fl(fma(beta,mem,cur) - prev_spk) ----
#pragma unroll
        for (int k = 0; k < H2; k++) {
            float mv = __fsub_rn(__fmaf_rn(BETA, mem2[k], c[k]), spk2[k]);
            mem2[k] = mv;
            spk2[k] = (mv > 1.0f) ? 1.0f : 0.0f;
        }

        // ---- stores (float2, 8B aligned) ----
#pragma unroll
        for (int k = 0; k < 5; k++) {
            float2 sv; sv.x = spk2[2 * k]; sv.y = spk2[2 * k + 1];
            *(float2*)(spkout + 2 * k) = sv;
            float2 mv; mv.x = mem2[2 * k]; mv.y = mem2[2 * k + 1];
            *(float2*)(memout + 2 * k) = mv;
        }

        spkout += step_stride;
        memout += step_stride;
    }
}

extern "C" void kernel_launch(void* const* d_in, const int* in_sizes, int n_in,
                              void* d_out, int out_size) {
    const float* x  = (const float*)d_in[0];
    const float* W1 = (const float*)d_in[1];
    const float* b1 = (const float*)d_in[2];
    const float* W2 = (const float*)d_in[3];
    const float* b2 = (const float*)d_in[4];
    float* out = (float*)d_out;
    const int B = in_sizes[0] / NIN;

    static bool attr_set = false;  // idempotent attribute, not a work guard
    if (!attr_set) {
        cudaFuncSetAttribute(snn_kernel,
                             cudaFuncAttributeMaxDynamicSharedMemorySize,
                             SMEM_BYTES);
        attr_set = true;
    }

    const int grid = (B + TPB - 1) / TPB;
    snn_kernel<<<grid, TPB, SMEM_BYTES>>>(x, W1, b1, W2, b2, out, B);
}